// round 12
// baseline (speedup 1.0000x reference)
#include <cuda_runtime.h>

#define NBINS_ABS 1024
#define ABS_OFF   512
#define NTAB      195
#define NHA       196
#define LBINS     64                 // local bins: floor(5x) in [-32,31]
#define LBASE     (ABS_OFF - 32)
#define MAGIC_F   8388640.0f         // 2^23 + 32
#define MAGIC_U   0x4B000000u        // bits(2^23)
#define GRID_N    1184               // 148 SMs * 8

__device__ unsigned int g_hist[NBINS_ABS];
__device__ int          g_minneg;    // max over outliers of (4096 - floor(5x)); 0 = none
__device__ double       g_acc;
__device__ float2       g_table[NTAB];   // (A, B): nloss = t*A + B
__device__ float        g_nvmn5;         // -(vmin+0.5)*5
__device__ unsigned int g_tick1;
__device__ unsigned int g_tick2;

struct f8 { float4 a, b; };

// ---------------------------------------------------------------- 32B load
static __device__ __forceinline__ f8 ldg8(const float* p) {
    f8 v;
    asm("ld.global.nc.L2::evict_last.v8.b32 {%0,%1,%2,%3,%4,%5,%6,%7}, [%8];"
        : "=f"(v.a.x), "=f"(v.a.y), "=f"(v.a.z), "=f"(v.a.w),
          "=f"(v.b.x), "=f"(v.b.y), "=f"(v.b.z), "=f"(v.b.w)
        : "l"(p));
    return v;
}

// ---------------------------------------------------------------- slow path
static __device__ __noinline__ void hbin_slow(float f) {
    int b = __float2int_rd(f * 5.0f);
    atomicAdd(&g_hist[min(NBINS_ABS - 1, max(0, b + ABS_OFF))], 1u);
    atomicMax(&g_minneg, 4096 - b);
}

// conflict-free per-thread byte counter: thread owns word (l>>2)*256+tid, byte (l&3).
// addr = ((u&0xFC)<<8) | (u&3) | (tid<<2);  bank = tid&31 always.
static __device__ __forceinline__ unsigned int haddr(unsigned int u, int tq) {
    return ((u & 0xFCu) << 8) | ((u & 3u) | (unsigned int)tq);
}

static __device__ __forceinline__ void hq(const float4& a, unsigned char* sh8, int tq) {
    unsigned int u0 = __float_as_uint(__fmaf_rd(a.x, 5.0f, MAGIC_F));
    unsigned int u1 = __float_as_uint(__fmaf_rd(a.y, 5.0f, MAGIC_F));
    unsigned int u2 = __float_as_uint(__fmaf_rd(a.z, 5.0f, MAGIC_F));
    unsigned int u3 = __float_as_uint(__fmaf_rd(a.w, 5.0f, MAGIC_F));
    if (((u0 | u1 | u2 | u3) - MAGIC_U) < (unsigned int)LBINS) {
        sh8[haddr(u0, tq)]++;
        sh8[haddr(u1, tq)]++;
        sh8[haddr(u2, tq)]++;
        sh8[haddr(u3, tq)]++;
    } else {
        if (u0 - MAGIC_U < LBINS) sh8[haddr(u0, tq)]++; else hbin_slow(a.x);
        if (u1 - MAGIC_U < LBINS) sh8[haddr(u1, tq)]++; else hbin_slow(a.y);
        if (u2 - MAGIC_U < LBINS) sh8[haddr(u2, tq)]++; else hbin_slow(a.z);
        if (u3 - MAGIC_U < LBINS) sh8[haddr(u3, tq)]++; else hbin_slow(a.w);
    }
}

// ---------------------------------------------------------------- pass 1: histogram + last-block table build
__global__ void __launch_bounds__(256, 8) k_hist(const float* __restrict__ xp, int n, double inv_n) {
    __shared__ unsigned char sh8[16 * 1024];
    const int tid  = threadIdx.x;
    const int lane = tid & 31;
    const int wid  = tid >> 5;
    const int tq   = tid << 2;

    #pragma unroll
    for (int i = 0; i < 16; i++)
        ((unsigned int*)sh8)[i * 256 + tid] = 0u;
    __syncthreads();

    const int n8 = n >> 3;
    const int stride = gridDim.x * blockDim.x;

    for (int i = blockIdx.x * blockDim.x + tid; i < n8; i += stride) {
        f8 v = ldg8(xp + 8 * (long long)i);
        hq(v.a, sh8, tq);
        hq(v.b, sh8, tq);
    }
    if (blockIdx.x == 0 && tid < (n & 7)) hbin_slow(xp[(n & ~7) + tid]);
    __syncthreads();

    // merge: row r holds bins 4r..4r+3; per-byte extraction via dp4a
    for (int r = wid; r < 16; r += 8) {
        const unsigned int* row = (const unsigned int*)sh8 + r * 256;
        unsigned int a0 = 0, a1 = 0, a2 = 0, a3 = 0;
        #pragma unroll
        for (int j = 0; j < 8; j++) {
            unsigned int w = row[lane + 32 * j];
            a0 = __dp4a(w, 0x00000001u, a0);
            a1 = __dp4a(w, 0x00000100u, a1);
            a2 = __dp4a(w, 0x00010000u, a2);
            a3 = __dp4a(w, 0x01000000u, a3);
        }
        #pragma unroll
        for (int o = 16; o; o >>= 1) {
            a0 += __shfl_xor_sync(0xFFFFFFFFu, a0, o);
            a1 += __shfl_xor_sync(0xFFFFFFFFu, a1, o);
            a2 += __shfl_xor_sync(0xFFFFFFFFu, a2, o);
            a3 += __shfl_xor_sync(0xFFFFFFFFu, a3, o);
        }
        if (lane == 0) {
            int b = LBASE + 4 * r;
            if (a0) atomicAdd(&g_hist[b + 0], a0);
            if (a1) atomicAdd(&g_hist[b + 1], a1);
            if (a2) atomicAdd(&g_hist[b + 2], a2);
            if (a3) atomicAdd(&g_hist[b + 3], a3);
        }
    }

    // allow the dependent k_loss grid to start spinning up now
    cudaTriggerProgrammaticLaunchCompletion();

    // ---- ticket: last block builds the tables ----
    __shared__ unsigned int s_islast;
    if (tid == 0) {
        __threadfence();
        s_islast = (atomicInc(&g_tick1, gridDim.x - 1) == gridDim.x - 1);
    }
    __syncthreads();
    if (!s_islast) return;

    __shared__ unsigned int s_cum[NBINS_ABS];
    __shared__ unsigned int s_wsum[8];
    __shared__ float s_ha[NHA];
    __shared__ int s_b0;
    if (tid == 0) {
        int mn = g_minneg; g_minneg = 0;
        s_b0 = mn ? (4096 - mn) + ABS_OFF : 0x7FFFFFFF;
    }
    __syncthreads();

    unsigned int h0 = g_hist[4 * tid + 0], h1 = g_hist[4 * tid + 1];
    unsigned int h2 = g_hist[4 * tid + 2], h3 = g_hist[4 * tid + 3];
    g_hist[4 * tid + 0] = 0u; g_hist[4 * tid + 1] = 0u;   // reset for replay
    g_hist[4 * tid + 2] = 0u; g_hist[4 * tid + 3] = 0u;
    if (h0 | h1 | h2 | h3)
        atomicMin(&s_b0, 4 * tid + (h0 ? 0 : h1 ? 1 : h2 ? 2 : 3));

    unsigned int p0 = h0, p1 = p0 + h1, p2 = p1 + h2, S = p2 + h3;
    unsigned int x = S;
    #pragma unroll
    for (int o = 1; o < 32; o <<= 1) {
        unsigned int y = __shfl_up_sync(0xFFFFFFFFu, x, o);
        if (lane >= o) x += y;
    }
    if (lane == 31) s_wsum[wid] = x;
    unsigned int excl = x - S;
    __syncthreads();
    if (tid == 0) {
        unsigned int a = 0;
        #pragma unroll
        for (int w = 0; w < 8; w++) { unsigned int t = s_wsum[w]; s_wsum[w] = a; a += t; }
    }
    __syncthreads();
    unsigned int boff = s_wsum[wid] + excl;
    s_cum[4 * tid + 0] = boff + p0;
    s_cum[4 * tid + 1] = boff + p1;
    s_cum[4 * tid + 2] = boff + p2;
    s_cum[4 * tid + 3] = boff + S;
    __syncthreads();

    const unsigned int total = s_cum[NBINS_ABS - 1];
    int b0rel = s_b0 - ABS_OFF;                 // floor(5 * xmin)
    int fd = (b0rel >= 0) ? (b0rel / 5) : -((-b0rel + 4) / 5);
    int vmin_i = fd - 1;
    int hbase = 5 * vmin_i + ABS_OFF;

    if (tid < NHA) {
        int j = tid;
        double lo, hi;
        if (j == 0) lo = 0.0;
        else {
            int k = hbase + j - 1;
            lo = (k < 0) ? 0.0 : (double)((k >= NBINS_ABS) ? total : s_cum[k]);
        }
        if (j >= NHA - 1) hi = (double)total;
        else {
            int k = hbase + j + 4;
            hi = (k < 0) ? 0.0 : (double)((k >= NBINS_ABS) ? total : s_cum[k]);
        }
        s_ha[j] = (float)((hi - lo) * inv_n);
    }
    __syncthreads();
    if (tid < NTAB) {
        float A = s_ha[tid + 1] - s_ha[tid];
        float B = (float)((double)s_ha[tid] + 1e-8 - (double)tid * (double)A);
        g_table[tid] = make_float2(A, B);
    }
    if (tid == 0) g_nvmn5 = -(((float)vmin_i + 0.5f) * 5.0f);
}

// ---------------------------------------------------------------- pass 2: lean loss (PDL secondary)
static __device__ __forceinline__ float nloss_of(float xv, float nvmn5, const float2* tab) {
    float t = fmaf(xv, 5.0f, nvmn5);     // >= 2.5 since x >= min
    int i = min(__float2int_rd(t), NTAB - 1);
    float2 ab = tab[i];
    return fmaf(t, ab.x, ab.y);
}

static __device__ __forceinline__ void prod4r(const float4& v, float nvmn5,
                                              const float2* tab, unsigned int& eraw, float& m) {
    float p = nloss_of(v.x, nvmn5, tab) * nloss_of(v.y, nvmn5, tab)
            * nloss_of(v.z, nvmn5, tab) * nloss_of(v.w, nvmn5, tab);
    unsigned int ub = __float_as_uint(p);
    eraw = ub >> 23;
    m = __uint_as_float((ub & 0x007FFFFFu) | 0x3F800000u);
}

__global__ void __launch_bounds__(256, 8) k_loss(const float* __restrict__ xp, int n,
                                                 double inv_n, float* __restrict__ out) {
    // wait for k_hist grid to fully complete (table + g_nvmn5 visible after this)
    cudaGridDependencySynchronize();

    __shared__ float2 tab[NTAB];
    for (int i = threadIdx.x; i < NTAB; i += blockDim.x) tab[i] = g_table[i];
    __syncthreads();
    const float nvmn5 = g_nvmn5;

    const int n8 = n >> 3;
    const int tid = blockIdx.x * blockDim.x + threadIdx.x;
    const int stride = gridDim.x * blockDim.x;

    float acc = 0.0f;          // sum of log2(mantissa products)
    unsigned int acc_e = 0u;   // sum of raw biased exponents (2 per iter)
    for (int i = tid; i < n8; i += stride) {
        f8 v = ldg8(xp + 8 * (long long)i);     // forward traversal
        unsigned int ea, eb; float ma, mb;
        prod4r(v.a, nvmn5, tab, ea, ma);
        prod4r(v.b, nvmn5, tab, eb, mb);
        acc_e += ea + eb;
        acc += __log2f(ma * mb);
    }
    // deferred bias: 2 exponents per iteration, each biased +127
    int iters = (tid < n8) ? ((n8 - 1 - tid) / stride + 1) : 0;
    acc += (float)((int)acc_e - 254 * iters);

    if (blockIdx.x == 0 && threadIdx.x < (n & 7)) {
        float f = xp[(n & ~7) + threadIdx.x];
        acc += __log2f(nloss_of(f, nvmn5, tab));
    }

    #pragma unroll
    for (int o = 16; o; o >>= 1) acc += __shfl_xor_sync(0xFFFFFFFFu, acc, o);
    __shared__ float ws[8];
    if ((threadIdx.x & 31) == 0) ws[threadIdx.x >> 5] = acc;
    __syncthreads();
    if (threadIdx.x < 32) {
        float a = (threadIdx.x < 8) ? ws[threadIdx.x] : 0.0f;
        #pragma unroll
        for (int o = 4; o; o >>= 1) a += __shfl_xor_sync(0xFFFFFFFFu, a, o);
        if (threadIdx.x == 0) atomicAdd(&g_acc, (double)a);
    }

    // ---- ticket: last block finalizes ----
    if (threadIdx.x == 0) {
        __threadfence();
        if (atomicInc(&g_tick2, gridDim.x - 1) == gridDim.x - 1) {
            double a = g_acc;
            g_acc = 0.0;
            out[0] = (float)(-a * inv_n);
        }
    }
}

// ---------------------------------------------------------------- launch
extern "C" void kernel_launch(void* const* d_in, const int* in_sizes, int n_in,
                              void* d_out, int out_size) {
    const float* x = (const float*)d_in[0];
    const int n = in_sizes[0];
    const double inv_n = 1.0 / (double)n;

    k_hist<<<GRID_N, 256>>>(x, n, inv_n);

    // k_loss as PDL secondary: may begin block ramp-up while k_hist drains;
    // cudaGridDependencySynchronize() inside orders table reads.
    cudaLaunchConfig_t cfg = {};
    cfg.gridDim  = dim3(GRID_N, 1, 1);
    cfg.blockDim = dim3(256, 1, 1);
    cfg.dynamicSmemBytes = 0;
    cfg.stream = 0;
    cudaLaunchAttribute attr[1];
    attr[0].id = cudaLaunchAttributeProgrammaticStreamSerialization;
    attr[0].val.programmaticStreamSerializationAllowed = 1;
    cfg.attrs = attr;
    cfg.numAttrs = 1;
    cudaLaunchKernelEx(&cfg, k_loss, x, n, inv_n, (float*)d_out);
}

// round 13
// speedup vs baseline: 1.1339x; 1.1339x over previous
#include <cuda_runtime.h>

#define NBINS_ABS 1024
#define ABS_OFF   512
#define NTAB      195
#define NHA       196
#define LBINS     64                 // local bins: floor(5x) in [-32,31]
#define LBASE     (ABS_OFF - 32)
#define MAGIC_F   8388640.0f         // 2^23 + 32
#define MAGIC_U   0x4B000000u        // bits(2^23)
#define MAGIC2_F  4196349.5f         // 2^22 + 2048 - 2.5   (ulp 0.5 -> exact)
#define MAGIC2_U  0x4A800000u        // bits(2^22)
#define GRID_N    1184               // 148 SMs * 8

__device__ unsigned int g_hist[NBINS_ABS];
__device__ int          g_minneg;    // max over outliers of (4096 - floor(5x)); 0 = none
__device__ double       g_acc;
__device__ float2       g_table[NTAB];   // (A, B): nloss = t*A + B
__device__ float        g_nvmn5;         // -(vmin+0.5)*5
__device__ unsigned int g_isub;          // MAGIC2_U + 4096 + 10*vmin
__device__ unsigned int g_tick1;
__device__ unsigned int g_tick2;

struct f8 { float4 a, b; };

// ---------------------------------------------------------------- 32B load
static __device__ __forceinline__ f8 ldg8(const float* p) {
    f8 v;
    asm("ld.global.nc.L2::evict_last.v8.b32 {%0,%1,%2,%3,%4,%5,%6,%7}, [%8];"
        : "=f"(v.a.x), "=f"(v.a.y), "=f"(v.a.z), "=f"(v.a.w),
          "=f"(v.b.x), "=f"(v.b.y), "=f"(v.b.z), "=f"(v.b.w)
        : "l"(p));
    return v;
}

// ---------------------------------------------------------------- slow path
static __device__ __noinline__ void hbin_slow(float f) {
    int b = __float2int_rd(f * 5.0f);
    atomicAdd(&g_hist[min(NBINS_ABS - 1, max(0, b + ABS_OFF))], 1u);
    atomicMax(&g_minneg, 4096 - b);
}

// conflict-free per-thread byte counter: thread owns word (l>>2)*256+tid, byte (l&3).
static __device__ __forceinline__ unsigned int haddr(unsigned int u, int tq) {
    return ((u & 0xFCu) << 8) | ((u & 3u) | (unsigned int)tq);
}

static __device__ __forceinline__ void hq(const float4& a, unsigned char* sh8, int tq) {
    unsigned int u0 = __float_as_uint(__fmaf_rd(a.x, 5.0f, MAGIC_F));
    unsigned int u1 = __float_as_uint(__fmaf_rd(a.y, 5.0f, MAGIC_F));
    unsigned int u2 = __float_as_uint(__fmaf_rd(a.z, 5.0f, MAGIC_F));
    unsigned int u3 = __float_as_uint(__fmaf_rd(a.w, 5.0f, MAGIC_F));
    if (((u0 | u1 | u2 | u3) - MAGIC_U) < (unsigned int)LBINS) {
        sh8[haddr(u0, tq)]++;
        sh8[haddr(u1, tq)]++;
        sh8[haddr(u2, tq)]++;
        sh8[haddr(u3, tq)]++;
    } else {
        if (u0 - MAGIC_U < LBINS) sh8[haddr(u0, tq)]++; else hbin_slow(a.x);
        if (u1 - MAGIC_U < LBINS) sh8[haddr(u1, tq)]++; else hbin_slow(a.y);
        if (u2 - MAGIC_U < LBINS) sh8[haddr(u2, tq)]++; else hbin_slow(a.z);
        if (u3 - MAGIC_U < LBINS) sh8[haddr(u3, tq)]++; else hbin_slow(a.w);
    }
}

// ---------------------------------------------------------------- pass 1: histogram + last-block table build
__global__ void __launch_bounds__(256, 8) k_hist(const float* __restrict__ xp, int n, double inv_n) {
    __shared__ unsigned char sh8[16 * 1024];
    const int tid  = threadIdx.x;
    const int lane = tid & 31;
    const int wid  = tid >> 5;
    const int tq   = tid << 2;

    #pragma unroll
    for (int i = 0; i < 16; i++)
        ((unsigned int*)sh8)[i * 256 + tid] = 0u;
    __syncthreads();

    const int n8 = n >> 3;
    const int stride = gridDim.x * blockDim.x;

    for (int i = blockIdx.x * blockDim.x + tid; i < n8; i += stride) {
        f8 v = ldg8(xp + 8 * (long long)i);
        hq(v.a, sh8, tq);
        hq(v.b, sh8, tq);
    }
    if (blockIdx.x == 0 && tid < (n & 7)) hbin_slow(xp[(n & ~7) + tid]);
    __syncthreads();

    for (int r = wid; r < 16; r += 8) {
        const unsigned int* row = (const unsigned int*)sh8 + r * 256;
        unsigned int a0 = 0, a1 = 0, a2 = 0, a3 = 0;
        #pragma unroll
        for (int j = 0; j < 8; j++) {
            unsigned int w = row[lane + 32 * j];
            a0 = __dp4a(w, 0x00000001u, a0);
            a1 = __dp4a(w, 0x00000100u, a1);
            a2 = __dp4a(w, 0x00010000u, a2);
            a3 = __dp4a(w, 0x01000000u, a3);
        }
        #pragma unroll
        for (int o = 16; o; o >>= 1) {
            a0 += __shfl_xor_sync(0xFFFFFFFFu, a0, o);
            a1 += __shfl_xor_sync(0xFFFFFFFFu, a1, o);
            a2 += __shfl_xor_sync(0xFFFFFFFFu, a2, o);
            a3 += __shfl_xor_sync(0xFFFFFFFFu, a3, o);
        }
        if (lane == 0) {
            int b = LBASE + 4 * r;
            if (a0) atomicAdd(&g_hist[b + 0], a0);
            if (a1) atomicAdd(&g_hist[b + 1], a1);
            if (a2) atomicAdd(&g_hist[b + 2], a2);
            if (a3) atomicAdd(&g_hist[b + 3], a3);
        }
    }

    // ---- ticket: last block builds the tables ----
    __shared__ unsigned int s_islast;
    if (tid == 0) {
        __threadfence();
        s_islast = (atomicInc(&g_tick1, gridDim.x - 1) == gridDim.x - 1);
    }
    __syncthreads();
    if (!s_islast) return;

    __shared__ unsigned int s_cum[NBINS_ABS];
    __shared__ unsigned int s_wsum[8];
    __shared__ float s_ha[NHA];
    __shared__ int s_b0;
    if (tid == 0) {
        int mn = g_minneg; g_minneg = 0;
        s_b0 = mn ? (4096 - mn) + ABS_OFF : 0x7FFFFFFF;
    }
    __syncthreads();

    unsigned int h0 = g_hist[4 * tid + 0], h1 = g_hist[4 * tid + 1];
    unsigned int h2 = g_hist[4 * tid + 2], h3 = g_hist[4 * tid + 3];
    g_hist[4 * tid + 0] = 0u; g_hist[4 * tid + 1] = 0u;   // reset for replay
    g_hist[4 * tid + 2] = 0u; g_hist[4 * tid + 3] = 0u;
    if (h0 | h1 | h2 | h3)
        atomicMin(&s_b0, 4 * tid + (h0 ? 0 : h1 ? 1 : h2 ? 2 : 3));

    unsigned int p0 = h0, p1 = p0 + h1, p2 = p1 + h2, S = p2 + h3;
    unsigned int x = S;
    #pragma unroll
    for (int o = 1; o < 32; o <<= 1) {
        unsigned int y = __shfl_up_sync(0xFFFFFFFFu, x, o);
        if (lane >= o) x += y;
    }
    if (lane == 31) s_wsum[wid] = x;
    unsigned int excl = x - S;
    __syncthreads();
    if (tid == 0) {
        unsigned int a = 0;
        #pragma unroll
        for (int w = 0; w < 8; w++) { unsigned int t = s_wsum[w]; s_wsum[w] = a; a += t; }
    }
    __syncthreads();
    unsigned int boff = s_wsum[wid] + excl;
    s_cum[4 * tid + 0] = boff + p0;
    s_cum[4 * tid + 1] = boff + p1;
    s_cum[4 * tid + 2] = boff + p2;
    s_cum[4 * tid + 3] = boff + S;
    __syncthreads();

    const unsigned int total = s_cum[NBINS_ABS - 1];
    int b0rel = s_b0 - ABS_OFF;                 // floor(5 * xmin)
    int fd = (b0rel >= 0) ? (b0rel / 5) : -((-b0rel + 4) / 5);
    int vmin_i = fd - 1;
    int hbase = 5 * vmin_i + ABS_OFF;

    if (tid < NHA) {
        int j = tid;
        double lo, hi;
        if (j == 0) lo = 0.0;
        else {
            int k = hbase + j - 1;
            lo = (k < 0) ? 0.0 : (double)((k >= NBINS_ABS) ? total : s_cum[k]);
        }
        if (j >= NHA - 1) hi = (double)total;
        else {
            int k = hbase + j + 4;
            hi = (k < 0) ? 0.0 : (double)((k >= NBINS_ABS) ? total : s_cum[k]);
        }
        s_ha[j] = (float)((hi - lo) * inv_n);
    }
    __syncthreads();
    if (tid < NTAB) {
        float A = s_ha[tid + 1] - s_ha[tid];
        float B = (float)((double)s_ha[tid] + 1e-8 - (double)tid * (double)A);
        g_table[tid] = make_float2(A, B);
    }
    if (tid == 0) {
        g_nvmn5 = -(((float)vmin_i + 0.5f) * 5.0f);
        g_isub  = MAGIC2_U + 4096u + (unsigned int)(10 * vmin_i);
    }
}

// ---------------------------------------------------------------- pass 2: F2I-free loss
// i = floor(5x - 2.5) - 5*vmin via magic bits:  u = bits(RD(5x + 2^22 + 2048 - 2.5))
// u - isub = 2*i + {0,1}  ->  i = (u - isub) >> 1   (exact floor, ALU-only)
static __device__ __forceinline__ float nloss_of(float xv, float nvmn5, unsigned int isub,
                                                 const float2* tab) {
    float t = fmaf(xv, 5.0f, nvmn5);
    unsigned int u = __float_as_uint(__fmaf_rd(xv, 5.0f, MAGIC2_F));
    int i = min((int)((u - isub) >> 1), NTAB - 1);
    float2 ab = tab[i];
    return fmaf(t, ab.x, ab.y);
}

static __device__ __forceinline__ void prod4r(const float4& v, float nvmn5, unsigned int isub,
                                              const float2* tab, unsigned int& eraw, float& m) {
    float p = nloss_of(v.x, nvmn5, isub, tab) * nloss_of(v.y, nvmn5, isub, tab)
            * nloss_of(v.z, nvmn5, isub, tab) * nloss_of(v.w, nvmn5, isub, tab);
    unsigned int ub = __float_as_uint(p);
    eraw = ub >> 23;
    m = __uint_as_float((ub & 0x007FFFFFu) | 0x3F800000u);
}

__global__ void __launch_bounds__(256, 8) k_loss(const float* __restrict__ xp, int n,
                                                 double inv_n, float* __restrict__ out) {
    __shared__ float2 tab[NTAB];
    for (int i = threadIdx.x; i < NTAB; i += blockDim.x) tab[i] = g_table[i];
    __syncthreads();
    const float nvmn5 = g_nvmn5;
    const unsigned int isub = g_isub;

    const int n8 = n >> 3;
    const int tid = blockIdx.x * blockDim.x + threadIdx.x;
    const int stride = gridDim.x * blockDim.x;

    float acc = 0.0f;
    unsigned int acc_e = 0u;
    for (int i = tid; i < n8; i += stride) {
        f8 v = ldg8(xp + 8 * (long long)(n8 - 1 - i));
        unsigned int ea, eb; float ma, mb;
        prod4r(v.a, nvmn5, isub, tab, ea, ma);
        prod4r(v.b, nvmn5, isub, tab, eb, mb);
        acc_e += ea + eb;
        acc += __log2f(ma * mb);
    }
    int iters = (tid < n8) ? ((n8 - 1 - tid) / stride + 1) : 0;
    acc += (float)((int)acc_e - 254 * iters);

    if (blockIdx.x == 0 && threadIdx.x < (n & 7)) {
        float f = xp[(n & ~7) + threadIdx.x];
        acc += __log2f(nloss_of(f, nvmn5, isub, tab));
    }

    #pragma unroll
    for (int o = 16; o; o >>= 1) acc += __shfl_xor_sync(0xFFFFFFFFu, acc, o);
    __shared__ float ws[8];
    if ((threadIdx.x & 31) == 0) ws[threadIdx.x >> 5] = acc;
    __syncthreads();
    if (threadIdx.x < 32) {
        float a = (threadIdx.x < 8) ? ws[threadIdx.x] : 0.0f;
        #pragma unroll
        for (int o = 4; o; o >>= 1) a += __shfl_xor_sync(0xFFFFFFFFu, a, o);
        if (threadIdx.x == 0) atomicAdd(&g_acc, (double)a);
    }

    // ---- ticket: last block finalizes ----
    if (threadIdx.x == 0) {
        __threadfence();
        if (atomicInc(&g_tick2, gridDim.x - 1) == gridDim.x - 1) {
            double a = g_acc;
            g_acc = 0.0;
            out[0] = (float)(-a * inv_n);
        }
    }
}

// ---------------------------------------------------------------- launch
extern "C" void kernel_launch(void* const* d_in, const int* in_sizes, int n_in,
                              void* d_out, int out_size) {
    const float* x = (const float*)d_in[0];
    const int n = in_sizes[0];
    const double inv_n = 1.0 / (double)n;

    k_hist<<<GRID_N, 256>>>(x, n, inv_n);
    k_loss<<<GRID_N, 256>>>(x, n, inv_n, (float*)d_out);
}